// round 1
// baseline (speedup 1.0000x reference)
#include <cuda_runtime.h>

#define NN 50000
#define EE 1600000
#define BBB 512

// ---------------- device scratch (static; no allocation) ----------------
__device__ float g_h[NN * 64];
__device__ float g_x[NN * 3];
__device__ float g_P1[NN * 64];
__device__ float g_P2[NN * 64];
__device__ float g_magg[NN * 64];
__device__ float g_dx[NN * 3];
__device__ int   g_hist[NN];
__device__ int   g_offs[NN + 1];
__device__ int   g_cur[NN];
__device__ int   g_col[EE];
__device__ float g_qsum[BBB];
__device__ float g_qx[BBB * 3];
__device__ float g_xsum[BBB * 3];
__device__ float g_cnt[BBB];

typedef unsigned long long u64;

// ---------------- packed f32x2 helpers (ptxas won't auto-fuse) ----------
__device__ __forceinline__ u64 fma2(u64 a, u64 b, u64 c) {
    u64 d;
    asm("fma.rn.f32x2 %0, %1, %2, %3;" : "=l"(d) : "l"(a), "l"(b), "l"(c));
    return d;
}
__device__ __forceinline__ u64 add2(u64 a, u64 b) {
    u64 d;
    asm("add.rn.f32x2 %0, %1, %2;" : "=l"(d) : "l"(a), "l"(b));
    return d;
}
__device__ __forceinline__ u64 pack2(float v) {
    u64 d;
    asm("mov.b64 %0, {%1, %1};" : "=l"(d) : "f"(v));
    return d;
}
__device__ __forceinline__ u64 packxy(float x, float y) {
    u64 d;
    asm("mov.b64 %0, {%1, %2};" : "=l"(d) : "f"(x), "f"(y));
    return d;
}
__device__ __forceinline__ float2 unpack(u64 v) {
    float2 f;
    asm("mov.b64 {%0, %1}, %2;" : "=f"(f.x), "=f"(f.y) : "l"(v));
    return f;
}

__device__ __forceinline__ float silu(float v) {
    float e = __expf(-v);
    return __fdividef(v, 1.0f + e);
}

// ---------------- init: h = emb[z], x = pos, zero accumulators ----------
__global__ void k_init(const int* __restrict__ z, const float* __restrict__ pos,
                       const float* __restrict__ emb, int N, int B) {
    int tid = blockIdx.x * blockDim.x + threadIdx.x;
    if (tid < N * 64) {
        int n = tid >> 6, k = tid & 63;
        g_h[tid] = emb[z[n] * 64 + k];
    }
    if (tid < N * 3) g_x[tid] = pos[tid];
    if (tid < N) { g_hist[tid] = 0; g_cur[tid] = 0; }
    if (tid < B) { g_qsum[tid] = 0.f; g_cnt[tid] = 0.f; }
    if (tid < B * 3) { g_qx[tid] = 0.f; g_xsum[tid] = 0.f; }
}

// ---------------- CSR build --------------------------------------------
__global__ void k_hist(const int* __restrict__ ei, int E) {
    int e = blockIdx.x * blockDim.x + threadIdx.x;
    if (e < E) atomicAdd(&g_hist[ei[e]], 1);
}

__global__ void k_scan(int N) {
    __shared__ int ss[1024];
    int tid = threadIdx.x;
    int ch = (N + 1023) / 1024;
    int base = tid * ch;
    int s = 0;
    for (int i = 0; i < ch; i++) {
        int idx = base + i;
        if (idx < N) s += g_hist[idx];
    }
    ss[tid] = s;
    __syncthreads();
    for (int off = 1; off < 1024; off <<= 1) {
        int v = (tid >= off) ? ss[tid - off] : 0;
        __syncthreads();
        ss[tid] += v;
        __syncthreads();
    }
    int run = (tid == 0) ? 0 : ss[tid - 1];
    for (int i = 0; i < ch; i++) {
        int idx = base + i;
        if (idx < N) { g_offs[idx] = run; run += g_hist[idx]; }
    }
    if (tid == 1023) g_offs[N] = ss[1023];
}

__global__ void k_scatter(const int* __restrict__ ei, int E) {
    int e = blockIdx.x * blockDim.x + threadIdx.x;
    if (e < E) {
        int r = ei[e];
        int idx = g_offs[r] + atomicAdd(&g_cur[r], 1);
        g_col[idx] = ei[E + e];
    }
}

// ---------------- per-layer node projections: P1 = h@W1a + eb1, P2 = h@W1b
__global__ __launch_bounds__(256) void k_proj(const float* __restrict__ eW1,
                                              const float* __restrict__ eb1, int N) {
    __shared__ u64 sA[64 * 32];
    __shared__ u64 sB[64 * 32];
    __shared__ u64 sb1[32];
    __shared__ __align__(16) float hb[8][64];
    int tid = threadIdx.x;
    const float* W1a = eW1;
    const float* W1b = eW1 + 64 * 64;
    for (int idx = tid; idx < 2048; idx += 256) {
        int i = idx >> 5, j2 = idx & 31;
        sA[idx] = packxy(W1a[i * 64 + 2 * j2], W1a[i * 64 + 2 * j2 + 1]);
        sB[idx] = packxy(W1b[i * 64 + 2 * j2], W1b[i * 64 + 2 * j2 + 1]);
    }
    if (tid < 32) sb1[tid] = packxy(eb1[2 * tid], eb1[2 * tid + 1]);
    __syncthreads();
    int wid = tid >> 5, lane = tid & 31;
    for (int n = blockIdx.x * 8 + wid; n < N; n += gridDim.x * 8) {
        __syncwarp();
        hb[wid][lane]      = g_h[n * 64 + lane];
        hb[wid][lane + 32] = g_h[n * 64 + lane + 32];
        __syncwarp();
        u64 a1a = sb1[lane], a1b = 0ull;
        u64 a2a = 0ull, a2b = 0ull;
        #pragma unroll 8
        for (int i = 0; i < 64; i += 2) {
            u64 v0 = pack2(hb[wid][i]);
            u64 v1 = pack2(hb[wid][i + 1]);
            a1a = fma2(v0, sA[i * 32 + lane], a1a);
            a2a = fma2(v0, sB[i * 32 + lane], a2a);
            a1b = fma2(v1, sA[(i + 1) * 32 + lane], a1b);
            a2b = fma2(v1, sB[(i + 1) * 32 + lane], a2b);
        }
        ((float2*)(g_P1 + n * 64))[lane] = unpack(add2(a1a, a1b));
        ((float2*)(g_P2 + n * 64))[lane] = unpack(add2(a2a, a2b));
    }
}

// ---------------- edge kernel: warp-per-node over CSR -------------------
__global__ __launch_bounds__(256) void k_edge(const float* __restrict__ eW1,
                                              const float* __restrict__ eW2,
                                              const float* __restrict__ eb2,
                                              const float* __restrict__ cW,
                                              const float* __restrict__ cb, int N) {
    __shared__ __align__(16) u64 sW2[64 * 32];
    __shared__ u64 sb2[32];
    __shared__ __align__(16) float swd[64];
    __shared__ float scw[64];
    __shared__ __align__(16) float stb[8][64];
    __shared__ float scb;
    int tid = threadIdx.x;
    for (int idx = tid; idx < 2048; idx += 256) {
        int i = idx >> 5, j2 = idx & 31;
        sW2[idx] = packxy(eW2[i * 64 + 2 * j2], eW2[i * 64 + 2 * j2 + 1]);
    }
    if (tid < 64) { swd[tid] = eW1[128 * 64 + tid]; scw[tid] = cW[tid]; }
    if (tid < 32) sb2[tid] = packxy(eb2[2 * tid], eb2[2 * tid + 1]);
    if (tid == 0) scb = cb[0];
    __syncthreads();
    int wid = tid >> 5, lane = tid & 31;
    float cbv = scb;
    for (int n = blockIdx.x * 8 + wid; n < N; n += gridDim.x * 8) {
        __syncwarp();
        stb[wid][lane]      = g_P1[n * 64 + lane];
        stb[wid][lane + 32] = g_P1[n * 64 + lane + 32];
        __syncwarp();
        float xn0 = g_x[n * 3], xn1 = g_x[n * 3 + 1], xn2 = g_x[n * 3 + 2];
        int s = g_offs[n], en = g_offs[n + 1];
        u64 macc[32];
        #pragma unroll
        for (int j = 0; j < 32; j++) macc[j] = 0ull;
        float dx0 = 0.f, dx1 = 0.f, dx2 = 0.f;
        for (int e = s + lane; e < en; e += 32) {
            int c = g_col[e];
            float r0 = xn0 - g_x[c * 3];
            float r1 = xn1 - g_x[c * 3 + 1];
            float r2 = xn2 - g_x[c * 3 + 2];
            float d2 = r0 * r0 + r1 * r1 + r2 * r2;
            const float4* p2 = (const float4*)(g_P2 + c * 64);
            u64 acc[32];
            #pragma unroll
            for (int j = 0; j < 32; j++) acc[j] = sb2[j];
            float4 curv = p2[0];
            #pragma unroll 2
            for (int q = 0; q < 16; q++) {
                float4 nxt = (q < 15) ? p2[q + 1] : curv;
                float4 tb = ((const float4*)stb[wid])[q];
                float4 wd = ((const float4*)swd)[q];
                float u0 = silu(tb.x + curv.x + d2 * wd.x);
                float u1 = silu(tb.y + curv.y + d2 * wd.y);
                float u2 = silu(tb.z + curv.z + d2 * wd.z);
                float u3 = silu(tb.w + curv.w + d2 * wd.w);
                u64 a0 = pack2(u0), a1 = pack2(u1), a2 = pack2(u2), a3 = pack2(u3);
                const ulonglong2* w0 = (const ulonglong2*)&sW2[(4 * q + 0) * 32];
                const ulonglong2* w1 = (const ulonglong2*)&sW2[(4 * q + 1) * 32];
                const ulonglong2* w2 = (const ulonglong2*)&sW2[(4 * q + 2) * 32];
                const ulonglong2* w3 = (const ulonglong2*)&sW2[(4 * q + 3) * 32];
                #pragma unroll
                for (int j = 0; j < 16; j++) {
                    ulonglong2 b0 = w0[j];
                    ulonglong2 b1 = w1[j];
                    ulonglong2 b2 = w2[j];
                    ulonglong2 b3 = w3[j];
                    acc[2 * j]     = fma2(a0, b0.x, acc[2 * j]);
                    acc[2 * j + 1] = fma2(a0, b0.y, acc[2 * j + 1]);
                    acc[2 * j]     = fma2(a1, b1.x, acc[2 * j]);
                    acc[2 * j + 1] = fma2(a1, b1.y, acc[2 * j + 1]);
                    acc[2 * j]     = fma2(a2, b2.x, acc[2 * j]);
                    acc[2 * j + 1] = fma2(a2, b2.y, acc[2 * j + 1]);
                    acc[2 * j]     = fma2(a3, b3.x, acc[2 * j]);
                    acc[2 * j + 1] = fma2(a3, b3.y, acc[2 * j + 1]);
                }
                curv = nxt;
            }
            float cd = cbv;
            #pragma unroll
            for (int j = 0; j < 32; j++) {
                float2 v = unpack(acc[j]);
                float m0 = silu(v.x), m1 = silu(v.y);
                macc[j] = add2(macc[j], packxy(m0, m1));
                cd += m0 * scw[2 * j] + m1 * scw[2 * j + 1];
            }
            float coef = tanhf(cd);
            dx0 += r0 * coef;
            dx1 += r1 * coef;
            dx2 += r2 * coef;
        }
        // warp reduction of macc (64 floats) and dx
        #pragma unroll
        for (int off = 16; off; off >>= 1) {
            #pragma unroll
            for (int j = 0; j < 32; j++)
                macc[j] = add2(macc[j], __shfl_xor_sync(0xffffffffu, macc[j], off));
            dx0 += __shfl_xor_sync(0xffffffffu, dx0, off);
            dx1 += __shfl_xor_sync(0xffffffffu, dx1, off);
            dx2 += __shfl_xor_sync(0xffffffffu, dx2, off);
        }
        if (lane == 0) {
            #pragma unroll
            for (int j = 0; j < 16; j++) {
                float2 va = unpack(macc[2 * j]);
                float2 vb = unpack(macc[2 * j + 1]);
                float4 o;
                o.x = va.x; o.y = va.y; o.z = vb.x; o.w = vb.y;
                ((float4*)(g_magg + n * 64))[j] = o;
            }
            g_dx[n * 3]     = dx0;
            g_dx[n * 3 + 1] = dx1;
            g_dx[n * 3 + 2] = dx2;
        }
    }
}

// ---------------- node update: h += MLP([h, magg]); x += dx -------------
__global__ __launch_bounds__(256) void k_node(const float* __restrict__ nW1,
                                              const float* __restrict__ nb1,
                                              const float* __restrict__ nW2,
                                              const float* __restrict__ nb2, int N) {
    __shared__ u64 sN1[128 * 32];
    __shared__ u64 sN2[64 * 32];
    __shared__ u64 snb1[32], snb2[32];
    __shared__ float inb[8][128];
    __shared__ float ub[8][64];
    int tid = threadIdx.x;
    for (int idx = tid; idx < 4096; idx += 256) {
        int i = idx >> 5, j2 = idx & 31;
        sN1[idx] = packxy(nW1[i * 64 + 2 * j2], nW1[i * 64 + 2 * j2 + 1]);
    }
    for (int idx = tid; idx < 2048; idx += 256) {
        int i = idx >> 5, j2 = idx & 31;
        sN2[idx] = packxy(nW2[i * 64 + 2 * j2], nW2[i * 64 + 2 * j2 + 1]);
    }
    if (tid < 32) {
        snb1[tid] = packxy(nb1[2 * tid], nb1[2 * tid + 1]);
        snb2[tid] = packxy(nb2[2 * tid], nb2[2 * tid + 1]);
    }
    __syncthreads();
    int wid = tid >> 5, lane = tid & 31;
    for (int n = blockIdx.x * 8 + wid; n < N; n += gridDim.x * 8) {
        __syncwarp();
        inb[wid][lane]      = g_h[n * 64 + lane];
        inb[wid][lane + 32] = g_h[n * 64 + lane + 32];
        inb[wid][lane + 64] = g_magg[n * 64 + lane];
        inb[wid][lane + 96] = g_magg[n * 64 + lane + 32];
        __syncwarp();
        u64 a0 = snb1[lane], a1 = 0ull, a2 = 0ull, a3 = 0ull;
        #pragma unroll 8
        for (int i = 0; i < 128; i += 4) {
            a0 = fma2(pack2(inb[wid][i]),     sN1[(i)*32 + lane],     a0);
            a1 = fma2(pack2(inb[wid][i + 1]), sN1[(i + 1) * 32 + lane], a1);
            a2 = fma2(pack2(inb[wid][i + 2]), sN1[(i + 2) * 32 + lane], a2);
            a3 = fma2(pack2(inb[wid][i + 3]), sN1[(i + 3) * 32 + lane], a3);
        }
        float2 t = unpack(add2(add2(a0, a1), add2(a2, a3)));
        ub[wid][2 * lane]     = silu(t.x);
        ub[wid][2 * lane + 1] = silu(t.y);
        __syncwarp();
        a0 = snb2[lane]; a1 = 0ull; a2 = 0ull; a3 = 0ull;
        #pragma unroll 8
        for (int i = 0; i < 64; i += 4) {
            a0 = fma2(pack2(ub[wid][i]),     sN2[(i)*32 + lane],     a0);
            a1 = fma2(pack2(ub[wid][i + 1]), sN2[(i + 1) * 32 + lane], a1);
            a2 = fma2(pack2(ub[wid][i + 2]), sN2[(i + 2) * 32 + lane], a2);
            a3 = fma2(pack2(ub[wid][i + 3]), sN2[(i + 3) * 32 + lane], a3);
        }
        float2 dh = unpack(add2(add2(a0, a1), add2(a2, a3)));
        float2* hp = (float2*)(g_h + n * 64);
        float2 hv = hp[lane];
        hv.x += dh.x;
        hv.y += dh.y;
        hp[lane] = hv;
        if (lane < 3) g_x[n * 3 + lane] += g_dx[n * 3 + lane];
    }
}

// ---------------- final: q per node + batch reductions -------------------
__global__ __launch_bounds__(256) void k_q(const float* __restrict__ qW1,
                                           const float* __restrict__ qb1,
                                           const float* __restrict__ qW2,
                                           const float* __restrict__ qb2,
                                           const int* __restrict__ batch, int N) {
    __shared__ u64 sQ[64 * 32];
    __shared__ u64 sqb[32];
    __shared__ float sw2[64];
    __shared__ float hb[8][64];
    __shared__ float sqb2;
    int tid = threadIdx.x;
    for (int idx = tid; idx < 2048; idx += 256) {
        int i = idx >> 5, j2 = idx & 31;
        sQ[idx] = packxy(qW1[i * 64 + 2 * j2], qW1[i * 64 + 2 * j2 + 1]);
    }
    if (tid < 32) sqb[tid] = packxy(qb1[2 * tid], qb1[2 * tid + 1]);
    if (tid < 64) sw2[tid] = qW2[tid];
    if (tid == 0) sqb2 = qb2[0];
    __syncthreads();
    int wid = tid >> 5, lane = tid & 31;
    for (int n = blockIdx.x * 8 + wid; n < N; n += gridDim.x * 8) {
        __syncwarp();
        hb[wid][lane]      = g_h[n * 64 + lane];
        hb[wid][lane + 32] = g_h[n * 64 + lane + 32];
        __syncwarp();
        u64 a0 = sqb[lane], a1 = 0ull;
        #pragma unroll 8
        for (int i = 0; i < 64; i += 2) {
            a0 = fma2(pack2(hb[wid][i]),     sQ[(i)*32 + lane],     a0);
            a1 = fma2(pack2(hb[wid][i + 1]), sQ[(i + 1) * 32 + lane], a1);
        }
        float2 t = unpack(add2(a0, a1));
        float cd = silu(t.x) * sw2[2 * lane] + silu(t.y) * sw2[2 * lane + 1];
        #pragma unroll
        for (int off = 16; off; off >>= 1) cd += __shfl_xor_sync(0xffffffffu, cd, off);
        if (lane == 0) {
            float q = cd + sqb2;
            int b = batch[n];
            float x0 = g_x[n * 3], x1 = g_x[n * 3 + 1], x2 = g_x[n * 3 + 2];
            atomicAdd(&g_qsum[b], q);
            atomicAdd(&g_qx[b * 3 + 0], q * x0);
            atomicAdd(&g_qx[b * 3 + 1], q * x1);
            atomicAdd(&g_qx[b * 3 + 2], q * x2);
            atomicAdd(&g_xsum[b * 3 + 0], x0);
            atomicAdd(&g_xsum[b * 3 + 1], x1);
            atomicAdd(&g_xsum[b * 3 + 2], x2);
            atomicAdd(&g_cnt[b], 1.0f);
        }
    }
}

__global__ void k_mu(float* __restrict__ out, int B) {
    int b = blockIdx.x * blockDim.x + threadIdx.x;
    if (b < B) {
        float c = fmaxf(g_cnt[b], 1.0f);
        float qs = g_qsum[b];
        #pragma unroll
        for (int k = 0; k < 3; k++) {
            float ctr = g_xsum[b * 3 + k] / c;
            out[b * 3 + k] = g_qx[b * 3 + k] - ctr * qs;
        }
    }
}

// ---------------- launch -------------------------------------------------
extern "C" void kernel_launch(void* const* d_in, const int* in_sizes, int n_in,
                              void* d_out, int out_size) {
    const int*   z    = (const int*)d_in[0];
    const float* pos  = (const float*)d_in[1];
    const int*   ei   = (const int*)d_in[2];
    const int*   bat  = (const int*)d_in[3];
    const float* emb  = (const float*)d_in[4];
    const float* eW1  = (const float*)d_in[5];
    const float* eb1  = (const float*)d_in[6];
    const float* eW2  = (const float*)d_in[7];
    const float* eb2  = (const float*)d_in[8];
    const float* cW   = (const float*)d_in[9];
    const float* cb   = (const float*)d_in[10];
    const float* nW1  = (const float*)d_in[11];
    const float* nb1  = (const float*)d_in[12];
    const float* nW2  = (const float*)d_in[13];
    const float* nb2  = (const float*)d_in[14];
    const float* qW1  = (const float*)d_in[15];
    const float* qb1  = (const float*)d_in[16];
    const float* qW2  = (const float*)d_in[17];
    const float* qb2  = (const float*)d_in[18];
    float* out = (float*)d_out;

    int N = in_sizes[0];
    int E = in_sizes[2] / 2;
    int B = out_size / 3;

    k_init<<<(N * 64 + 255) / 256, 256>>>(z, pos, emb, N, B);
    k_hist<<<(E + 255) / 256, 256>>>(ei, E);
    k_scan<<<1, 1024>>>(N);
    k_scatter<<<(E + 255) / 256, 256>>>(ei, E);

    const int nblk = 1184;  // 8 blocks per SM worth of node-warps, grid-stride
    for (int l = 0; l < 4; l++) {
        k_proj<<<nblk, 256>>>(eW1 + l * 129 * 64, eb1 + l * 64, N);
        k_edge<<<nblk, 256>>>(eW1 + l * 129 * 64, eW2 + l * 4096, eb2 + l * 64,
                              cW + l * 64, cb + l, N);
        k_node<<<nblk, 256>>>(nW1 + l * 128 * 64, nb1 + l * 64, nW2 + l * 4096,
                              nb2 + l * 64, N);
    }
    k_q<<<nblk, 256>>>(qW1, qb1, qW2, qb2, bat, N);
    k_mu<<<(B + 255) / 256, 256>>>(out, B);
}

// round 2
// speedup vs baseline: 1.4282x; 1.4282x over previous
#include <cuda_runtime.h>

#define NN 50000
#define EE 1600000
#define BBB 512

// ---------------- device scratch (static; no allocation) ----------------
__device__ float g_h[NN * 64];
__device__ float g_x[NN * 3];
__device__ float g_P1[NN * 64];
__device__ float g_P2[NN * 64];
__device__ float g_magg[NN * 64];
__device__ float g_dx[NN * 3];
__device__ int   g_hist[NN];
__device__ int   g_offs[NN + 1];
__device__ int   g_cur[NN];
__device__ int   g_col[EE];
__device__ float g_qsum[BBB];
__device__ float g_qx[BBB * 3];
__device__ float g_xsum[BBB * 3];
__device__ float g_cnt[BBB];

typedef unsigned long long u64;

// ---------------- packed f32x2 helpers (ptxas won't auto-fuse) ----------
__device__ __forceinline__ u64 fma2(u64 a, u64 b, u64 c) {
    u64 d;
    asm("fma.rn.f32x2 %0, %1, %2, %3;" : "=l"(d) : "l"(a), "l"(b), "l"(c));
    return d;
}
__device__ __forceinline__ u64 add2(u64 a, u64 b) {
    u64 d;
    asm("add.rn.f32x2 %0, %1, %2;" : "=l"(d) : "l"(a), "l"(b));
    return d;
}
__device__ __forceinline__ u64 pack2(float v) {
    u64 d;
    asm("mov.b64 %0, {%1, %1};" : "=l"(d) : "f"(v));
    return d;
}
__device__ __forceinline__ u64 packxy(float x, float y) {
    u64 d;
    asm("mov.b64 %0, {%1, %2};" : "=l"(d) : "f"(x), "f"(y));
    return d;
}
__device__ __forceinline__ float2 unpack(u64 v) {
    float2 f;
    asm("mov.b64 {%0, %1}, %2;" : "=f"(f.x), "=f"(f.y) : "l"(v));
    return f;
}
__device__ __forceinline__ u64 shfl_xor_u64(u64 v, int m) {
    float2 f = unpack(v);
    f.x = __shfl_xor_sync(0xffffffffu, f.x, m);
    f.y = __shfl_xor_sync(0xffffffffu, f.y, m);
    return packxy(f.x, f.y);
}

__device__ __forceinline__ float silu(float v) {
    float e = __expf(-v);
    return __fdividef(v, 1.0f + e);
}

// ---------------- init: h = emb[z], x = pos, zero accumulators ----------
__global__ void k_init(const int* __restrict__ z, const float* __restrict__ pos,
                       const float* __restrict__ emb, int N, int B) {
    int tid = blockIdx.x * blockDim.x + threadIdx.x;
    if (tid < N * 64) {
        int n = tid >> 6, k = tid & 63;
        g_h[tid] = emb[z[n] * 64 + k];
    }
    if (tid < N * 3) g_x[tid] = pos[tid];
    if (tid < N) { g_hist[tid] = 0; g_cur[tid] = 0; }
    if (tid < B) { g_qsum[tid] = 0.f; g_cnt[tid] = 0.f; }
    if (tid < B * 3) { g_qx[tid] = 0.f; g_xsum[tid] = 0.f; }
}

// ---------------- CSR build --------------------------------------------
__global__ void k_hist(const int* __restrict__ ei, int E) {
    int e = blockIdx.x * blockDim.x + threadIdx.x;
    if (e < E) atomicAdd(&g_hist[ei[e]], 1);
}

__global__ void k_scan(int N) {
    __shared__ int ss[1024];
    int tid = threadIdx.x;
    int ch = (N + 1023) / 1024;
    int base = tid * ch;
    int s = 0;
    for (int i = 0; i < ch; i++) {
        int idx = base + i;
        if (idx < N) s += g_hist[idx];
    }
    ss[tid] = s;
    __syncthreads();
    for (int off = 1; off < 1024; off <<= 1) {
        int v = (tid >= off) ? ss[tid - off] : 0;
        __syncthreads();
        ss[tid] += v;
        __syncthreads();
    }
    int run = (tid == 0) ? 0 : ss[tid - 1];
    for (int i = 0; i < ch; i++) {
        int idx = base + i;
        if (idx < N) { g_offs[idx] = run; run += g_hist[idx]; }
    }
    if (tid == 1023) g_offs[N] = ss[1023];
}

__global__ void k_scatter(const int* __restrict__ ei, int E) {
    int e = blockIdx.x * blockDim.x + threadIdx.x;
    if (e < E) {
        int r = ei[e];
        int idx = g_offs[r] + atomicAdd(&g_cur[r], 1);
        g_col[idx] = ei[E + e];
    }
}

// ---------------- per-layer node projections: P1 = h@W1a + eb1, P2 = h@W1b
__global__ __launch_bounds__(256) void k_proj(const float* __restrict__ eW1,
                                              const float* __restrict__ eb1, int N) {
    __shared__ u64 sA[64 * 32];
    __shared__ u64 sB[64 * 32];
    __shared__ u64 sb1[32];
    __shared__ __align__(16) float hb[8][64];
    int tid = threadIdx.x;
    const float* W1a = eW1;
    const float* W1b = eW1 + 64 * 64;
    for (int idx = tid; idx < 2048; idx += 256) {
        int i = idx >> 5, j2 = idx & 31;
        sA[idx] = packxy(W1a[i * 64 + 2 * j2], W1a[i * 64 + 2 * j2 + 1]);
        sB[idx] = packxy(W1b[i * 64 + 2 * j2], W1b[i * 64 + 2 * j2 + 1]);
    }
    if (tid < 32) sb1[tid] = packxy(eb1[2 * tid], eb1[2 * tid + 1]);
    __syncthreads();
    int wid = tid >> 5, lane = tid & 31;
    for (int n = blockIdx.x * 8 + wid; n < N; n += gridDim.x * 8) {
        __syncwarp();
        hb[wid][lane]      = g_h[n * 64 + lane];
        hb[wid][lane + 32] = g_h[n * 64 + lane + 32];
        __syncwarp();
        u64 a1a = sb1[lane], a1b = 0ull;
        u64 a2a = 0ull, a2b = 0ull;
        #pragma unroll 8
        for (int i = 0; i < 64; i += 2) {
            u64 v0 = pack2(hb[wid][i]);
            u64 v1 = pack2(hb[wid][i + 1]);
            a1a = fma2(v0, sA[i * 32 + lane], a1a);
            a2a = fma2(v0, sB[i * 32 + lane], a2a);
            a1b = fma2(v1, sA[(i + 1) * 32 + lane], a1b);
            a2b = fma2(v1, sB[(i + 1) * 32 + lane], a2b);
        }
        ((float2*)(g_P1 + n * 64))[lane] = unpack(add2(a1a, a1b));
        ((float2*)(g_P2 + n * 64))[lane] = unpack(add2(a2a, a2b));
    }
}

// ---------------- edge kernel: warp-per-node over CSR -------------------
// 128 threads (4 node-warps), >=4 blocks/SM. Per pass of 32 edges the edge-m
// vectors are transpose-reduced across the warp (lane l keeps channel pair
// (2l, 2l+1)), so only ONE u64 aggregation register stays live in the loop.
__global__ __launch_bounds__(128, 4) void k_edge(const float* __restrict__ eW1,
                                                 const float* __restrict__ eW2,
                                                 const float* __restrict__ eb2,
                                                 const float* __restrict__ cW,
                                                 const float* __restrict__ cb, int N) {
    __shared__ __align__(16) u64 sW2[64 * 32];
    __shared__ u64 sb2[32];
    __shared__ __align__(16) float swd[64];
    __shared__ float scw[64];
    __shared__ __align__(16) float stb[4][64];
    __shared__ float scb;
    int tid = threadIdx.x;
    for (int idx = tid; idx < 2048; idx += 128) {
        int i = idx >> 5, j2 = idx & 31;
        sW2[idx] = packxy(eW2[i * 64 + 2 * j2], eW2[i * 64 + 2 * j2 + 1]);
    }
    if (tid < 64) { swd[tid] = eW1[128 * 64 + tid]; scw[tid] = cW[tid]; }
    if (tid < 32) sb2[tid] = packxy(eb2[2 * tid], eb2[2 * tid + 1]);
    if (tid == 0) scb = cb[0];
    __syncthreads();
    int wid = tid >> 5, lane = tid & 31;
    float cbv = scb;
    for (int n = blockIdx.x * 4 + wid; n < N; n += gridDim.x * 4) {
        __syncwarp();
        stb[wid][lane]      = g_P1[n * 64 + lane];
        stb[wid][lane + 32] = g_P1[n * 64 + lane + 32];
        __syncwarp();
        float xn0 = g_x[n * 3], xn1 = g_x[n * 3 + 1], xn2 = g_x[n * 3 + 2];
        int s = g_offs[n], en = g_offs[n + 1];
        u64 macc2 = 0ull;
        float dx0 = 0.f, dx1 = 0.f, dx2 = 0.f;
        for (int base = s; base < en; base += 32) {
            int e = base + lane;
            bool valid = (e < en);
            int ee = valid ? e : (en - 1);
            int c = g_col[ee];
            float r0 = xn0 - g_x[c * 3];
            float r1 = xn1 - g_x[c * 3 + 1];
            float r2 = xn2 - g_x[c * 3 + 2];
            float d2 = r0 * r0 + r1 * r1 + r2 * r2;
            const float4* p2 = (const float4*)(g_P2 + c * 64);
            u64 acc[32];
            #pragma unroll
            for (int j = 0; j < 32; j++) acc[j] = sb2[j];
            float4 curv = p2[0];
            #pragma unroll 2
            for (int q = 0; q < 16; q++) {
                float4 nxt = (q < 15) ? p2[q + 1] : curv;
                float4 tb = ((const float4*)stb[wid])[q];
                float4 wd = ((const float4*)swd)[q];
                float u0 = silu(tb.x + curv.x + d2 * wd.x);
                float u1 = silu(tb.y + curv.y + d2 * wd.y);
                float u2 = silu(tb.z + curv.z + d2 * wd.z);
                float u3 = silu(tb.w + curv.w + d2 * wd.w);
                u64 a0 = pack2(u0), a1 = pack2(u1), a2 = pack2(u2), a3 = pack2(u3);
                const ulonglong2* w0 = (const ulonglong2*)&sW2[(4 * q + 0) * 32];
                const ulonglong2* w1 = (const ulonglong2*)&sW2[(4 * q + 1) * 32];
                const ulonglong2* w2 = (const ulonglong2*)&sW2[(4 * q + 2) * 32];
                const ulonglong2* w3 = (const ulonglong2*)&sW2[(4 * q + 3) * 32];
                #pragma unroll
                for (int j = 0; j < 16; j++) {
                    ulonglong2 b0 = w0[j];
                    ulonglong2 b1 = w1[j];
                    ulonglong2 b2 = w2[j];
                    ulonglong2 b3 = w3[j];
                    acc[2 * j]     = fma2(a0, b0.x, acc[2 * j]);
                    acc[2 * j + 1] = fma2(a0, b0.y, acc[2 * j + 1]);
                    acc[2 * j]     = fma2(a1, b1.x, acc[2 * j]);
                    acc[2 * j + 1] = fma2(a1, b1.y, acc[2 * j + 1]);
                    acc[2 * j]     = fma2(a2, b2.x, acc[2 * j]);
                    acc[2 * j + 1] = fma2(a2, b2.y, acc[2 * j + 1]);
                    acc[2 * j]     = fma2(a3, b3.x, acc[2 * j]);
                    acc[2 * j + 1] = fma2(a3, b3.y, acc[2 * j + 1]);
                }
                curv = nxt;
            }
            // silu -> m (in acc), edge coefficient
            float cd = cbv;
            #pragma unroll
            for (int j = 0; j < 32; j++) {
                float2 v = unpack(acc[j]);
                float m0 = silu(v.x), m1 = silu(v.y);
                acc[j] = packxy(m0, m1);
                cd += m0 * scw[2 * j] + m1 * scw[2 * j + 1];
            }
            float coef = tanhf(cd);
            if (valid) {
                dx0 += r0 * coef;
                dx1 += r1 * coef;
                dx2 += r2 * coef;
            } else {
                #pragma unroll
                for (int j = 0; j < 32; j++) acc[j] = 0ull;
            }
            // warp transpose-reduction: lane l ends with sum over the 32
            // edges of channel pair (2l, 2l+1) in acc[0]
            #pragma unroll
            for (int k = 16; k > 0; k >>= 1) {
                bool up = (lane & k);
                #pragma unroll
                for (int j = 0; j < k; j++) {
                    u64 send = up ? acc[j] : acc[j + k];
                    u64 keep = up ? acc[j + k] : acc[j];
                    u64 recv = shfl_xor_u64(send, k);
                    acc[j] = add2(keep, recv);
                }
            }
            macc2 = add2(macc2, acc[0]);
        }
        #pragma unroll
        for (int off = 16; off; off >>= 1) {
            dx0 += __shfl_xor_sync(0xffffffffu, dx0, off);
            dx1 += __shfl_xor_sync(0xffffffffu, dx1, off);
            dx2 += __shfl_xor_sync(0xffffffffu, dx2, off);
        }
        ((float2*)(g_magg + n * 64))[lane] = unpack(macc2);
        if (lane == 0) {
            g_dx[n * 3]     = dx0;
            g_dx[n * 3 + 1] = dx1;
            g_dx[n * 3 + 2] = dx2;
        }
    }
}

// ---------------- node update: h += MLP([h, magg]); x += dx -------------
__global__ __launch_bounds__(256) void k_node(const float* __restrict__ nW1,
                                              const float* __restrict__ nb1,
                                              const float* __restrict__ nW2,
                                              const float* __restrict__ nb2, int N) {
    __shared__ u64 sN1[128 * 32];
    __shared__ u64 sN2[64 * 32];
    __shared__ u64 snb1[32], snb2[32];
    __shared__ float inb[8][128];
    __shared__ float ub[8][64];
    int tid = threadIdx.x;
    for (int idx = tid; idx < 4096; idx += 256) {
        int i = idx >> 5, j2 = idx & 31;
        sN1[idx] = packxy(nW1[i * 64 + 2 * j2], nW1[i * 64 + 2 * j2 + 1]);
    }
    for (int idx = tid; idx < 2048; idx += 256) {
        int i = idx >> 5, j2 = idx & 31;
        sN2[idx] = packxy(nW2[i * 64 + 2 * j2], nW2[i * 64 + 2 * j2 + 1]);
    }
    if (tid < 32) {
        snb1[tid] = packxy(nb1[2 * tid], nb1[2 * tid + 1]);
        snb2[tid] = packxy(nb2[2 * tid], nb2[2 * tid + 1]);
    }
    __syncthreads();
    int wid = tid >> 5, lane = tid & 31;
    for (int n = blockIdx.x * 8 + wid; n < N; n += gridDim.x * 8) {
        __syncwarp();
        inb[wid][lane]      = g_h[n * 64 + lane];
        inb[wid][lane + 32] = g_h[n * 64 + lane + 32];
        inb[wid][lane + 64] = g_magg[n * 64 + lane];
        inb[wid][lane + 96] = g_magg[n * 64 + lane + 32];
        __syncwarp();
        u64 a0 = snb1[lane], a1 = 0ull, a2 = 0ull, a3 = 0ull;
        #pragma unroll 8
        for (int i = 0; i < 128; i += 4) {
            a0 = fma2(pack2(inb[wid][i]),     sN1[(i)*32 + lane],     a0);
            a1 = fma2(pack2(inb[wid][i + 1]), sN1[(i + 1) * 32 + lane], a1);
            a2 = fma2(pack2(inb[wid][i + 2]), sN1[(i + 2) * 32 + lane], a2);
            a3 = fma2(pack2(inb[wid][i + 3]), sN1[(i + 3) * 32 + lane], a3);
        }
        float2 t = unpack(add2(add2(a0, a1), add2(a2, a3)));
        ub[wid][2 * lane]     = silu(t.x);
        ub[wid][2 * lane + 1] = silu(t.y);
        __syncwarp();
        a0 = snb2[lane]; a1 = 0ull; a2 = 0ull; a3 = 0ull;
        #pragma unroll 8
        for (int i = 0; i < 64; i += 4) {
            a0 = fma2(pack2(ub[wid][i]),     sN2[(i)*32 + lane],     a0);
            a1 = fma2(pack2(ub[wid][i + 1]), sN2[(i + 1) * 32 + lane], a1);
            a2 = fma2(pack2(ub[wid][i + 2]), sN2[(i + 2) * 32 + lane], a2);
            a3 = fma2(pack2(ub[wid][i + 3]), sN2[(i + 3) * 32 + lane], a3);
        }
        float2 dh = unpack(add2(add2(a0, a1), add2(a2, a3)));
        float2* hp = (float2*)(g_h + n * 64);
        float2 hv = hp[lane];
        hv.x += dh.x;
        hv.y += dh.y;
        hp[lane] = hv;
        if (lane < 3) g_x[n * 3 + lane] += g_dx[n * 3 + lane];
    }
}

// ---------------- final: q per node + batch reductions -------------------
__global__ __launch_bounds__(256) void k_q(const float* __restrict__ qW1,
                                           const float* __restrict__ qb1,
                                           const float* __restrict__ qW2,
                                           const float* __restrict__ qb2,
                                           const int* __restrict__ batch, int N) {
    __shared__ u64 sQ[64 * 32];
    __shared__ u64 sqb[32];
    __shared__ float sw2[64];
    __shared__ float hb[8][64];
    __shared__ float sqb2;
    int tid = threadIdx.x;
    for (int idx = tid; idx < 2048; idx += 256) {
        int i = idx >> 5, j2 = idx & 31;
        sQ[idx] = packxy(qW1[i * 64 + 2 * j2], qW1[i * 64 + 2 * j2 + 1]);
    }
    if (tid < 32) sqb[tid] = packxy(qb1[2 * tid], qb1[2 * tid + 1]);
    if (tid < 64) sw2[tid] = qW2[tid];
    if (tid == 0) sqb2 = qb2[0];
    __syncthreads();
    int wid = tid >> 5, lane = tid & 31;
    for (int n = blockIdx.x * 8 + wid; n < N; n += gridDim.x * 8) {
        __syncwarp();
        hb[wid][lane]      = g_h[n * 64 + lane];
        hb[wid][lane + 32] = g_h[n * 64 + lane + 32];
        __syncwarp();
        u64 a0 = sqb[lane], a1 = 0ull;
        #pragma unroll 8
        for (int i = 0; i < 64; i += 2) {
            a0 = fma2(pack2(hb[wid][i]),     sQ[(i)*32 + lane],     a0);
            a1 = fma2(pack2(hb[wid][i + 1]), sQ[(i + 1) * 32 + lane], a1);
        }
        float2 t = unpack(add2(a0, a1));
        float cd = silu(t.x) * sw2[2 * lane] + silu(t.y) * sw2[2 * lane + 1];
        #pragma unroll
        for (int off = 16; off; off >>= 1) cd += __shfl_xor_sync(0xffffffffu, cd, off);
        if (lane == 0) {
            float q = cd + sqb2;
            int b = batch[n];
            float x0 = g_x[n * 3], x1 = g_x[n * 3 + 1], x2 = g_x[n * 3 + 2];
            atomicAdd(&g_qsum[b], q);
            atomicAdd(&g_qx[b * 3 + 0], q * x0);
            atomicAdd(&g_qx[b * 3 + 1], q * x1);
            atomicAdd(&g_qx[b * 3 + 2], q * x2);
            atomicAdd(&g_xsum[b * 3 + 0], x0);
            atomicAdd(&g_xsum[b * 3 + 1], x1);
            atomicAdd(&g_xsum[b * 3 + 2], x2);
            atomicAdd(&g_cnt[b], 1.0f);
        }
    }
}

__global__ void k_mu(float* __restrict__ out, int B) {
    int b = blockIdx.x * blockDim.x + threadIdx.x;
    if (b < B) {
        float c = fmaxf(g_cnt[b], 1.0f);
        float qs = g_qsum[b];
        #pragma unroll
        for (int k = 0; k < 3; k++) {
            float ctr = g_xsum[b * 3 + k] / c;
            out[b * 3 + k] = g_qx[b * 3 + k] - ctr * qs;
        }
    }
}

// ---------------- launch -------------------------------------------------
extern "C" void kernel_launch(void* const* d_in, const int* in_sizes, int n_in,
                              void* d_out, int out_size) {
    const int*   z    = (const int*)d_in[0];
    const float* pos  = (const float*)d_in[1];
    const int*   ei   = (const int*)d_in[2];
    const int*   bat  = (const int*)d_in[3];
    const float* emb  = (const float*)d_in[4];
    const float* eW1  = (const float*)d_in[5];
    const float* eb1  = (const float*)d_in[6];
    const float* eW2  = (const float*)d_in[7];
    const float* eb2  = (const float*)d_in[8];
    const float* cW   = (const float*)d_in[9];
    const float* cb   = (const float*)d_in[10];
    const float* nW1  = (const float*)d_in[11];
    const float* nb1  = (const float*)d_in[12];
    const float* nW2  = (const float*)d_in[13];
    const float* nb2  = (const float*)d_in[14];
    const float* qW1  = (const float*)d_in[15];
    const float* qb1  = (const float*)d_in[16];
    const float* qW2  = (const float*)d_in[17];
    const float* qb2  = (const float*)d_in[18];
    float* out = (float*)d_out;

    int N = in_sizes[0];
    int E = in_sizes[2] / 2;
    int B = out_size / 3;

    k_init<<<(N * 64 + 255) / 256, 256>>>(z, pos, emb, N, B);
    k_hist<<<(E + 255) / 256, 256>>>(ei, E);
    k_scan<<<1, 1024>>>(N);
    k_scatter<<<(E + 255) / 256, 256>>>(ei, E);

    const int nblk = 1184;
    const int eblk = 1184;  // 128-thread blocks, 4 node-warps each
    for (int l = 0; l < 4; l++) {
        k_proj<<<nblk, 256>>>(eW1 + l * 129 * 64, eb1 + l * 64, N);
        k_edge<<<eblk, 128>>>(eW1 + l * 129 * 64, eW2 + l * 4096, eb2 + l * 64,
                              cW + l * 64, cb + l, N);
        k_node<<<nblk, 256>>>(nW1 + l * 128 * 64, nb1 + l * 64, nW2 + l * 4096,
                              nb2 + l * 64, N);
    }
    k_q<<<nblk, 256>>>(qW1, qb1, qW2, qb2, bat, N);
    k_mu<<<(B + 255) / 256, 256>>>(out, B);
}

// round 3
// speedup vs baseline: 2.2040x; 1.5432x over previous
#include <cuda_runtime.h>

#define NN 50000
#define EE 1600000
#define BBB 512

// ---------------- device scratch (static; no allocation) ----------------
__device__ float g_h[NN * 64];
__device__ float g_x[NN * 3];
__device__ float g_P1[NN * 64];
__device__ float g_P2[NN * 64];
__device__ float g_magg[NN * 64];
__device__ float g_dx[NN * 3];
__device__ int   g_hist[NN];
__device__ int   g_offs[NN + 1];
__device__ int   g_cur[NN];
__device__ int   g_col[EE];
__device__ int   g_row[EE];
__device__ float g_qsum[BBB];
__device__ float g_qx[BBB * 3];
__device__ float g_xsum[BBB * 3];
__device__ float g_cnt[BBB];

typedef unsigned long long u64;

// ---------------- packed f32x2 helpers ----------------------------------
__device__ __forceinline__ u64 fma2(u64 a, u64 b, u64 c) {
    u64 d;
    asm("fma.rn.f32x2 %0, %1, %2, %3;" : "=l"(d) : "l"(a), "l"(b), "l"(c));
    return d;
}
__device__ __forceinline__ u64 add2(u64 a, u64 b) {
    u64 d;
    asm("add.rn.f32x2 %0, %1, %2;" : "=l"(d) : "l"(a), "l"(b));
    return d;
}
__device__ __forceinline__ u64 pack2(float v) {
    u64 d;
    asm("mov.b64 %0, {%1, %1};" : "=l"(d) : "f"(v));
    return d;
}
__device__ __forceinline__ u64 packxy(float x, float y) {
    u64 d;
    asm("mov.b64 %0, {%1, %2};" : "=l"(d) : "f"(x), "f"(y));
    return d;
}
__device__ __forceinline__ float2 unpack(u64 v) {
    float2 f;
    asm("mov.b64 {%0, %1}, %2;" : "=f"(f.x), "=f"(f.y) : "l"(v));
    return f;
}

__device__ __forceinline__ float silu(float v) {
    float e = __expf(-v);
    return __fdividef(v, 1.0f + e);
}

// ---------------- init ---------------------------------------------------
__global__ void k_init(const int* __restrict__ z, const float* __restrict__ pos,
                       const float* __restrict__ emb, int N, int B) {
    int tid = blockIdx.x * blockDim.x + threadIdx.x;
    if (tid < N * 64) {
        int n = tid >> 6, k = tid & 63;
        g_h[tid] = emb[z[n] * 64 + k];
    }
    if (tid < N * 3) g_x[tid] = pos[tid];
    if (tid < N) { g_hist[tid] = 0; g_cur[tid] = 0; }
    if (tid < B) { g_qsum[tid] = 0.f; g_cnt[tid] = 0.f; }
    if (tid < B * 3) { g_qx[tid] = 0.f; g_xsum[tid] = 0.f; }
}

// ---------------- CSR build ----------------------------------------------
__global__ void k_hist(const int* __restrict__ ei, int E) {
    int e = blockIdx.x * blockDim.x + threadIdx.x;
    if (e < E) atomicAdd(&g_hist[ei[e]], 1);
}

__global__ void k_scan(int N) {
    __shared__ int ss[1024];
    int tid = threadIdx.x;
    int ch = (N + 1023) / 1024;
    int base = tid * ch;
    int s = 0;
    for (int i = 0; i < ch; i++) {
        int idx = base + i;
        if (idx < N) s += g_hist[idx];
    }
    ss[tid] = s;
    __syncthreads();
    for (int off = 1; off < 1024; off <<= 1) {
        int v = (tid >= off) ? ss[tid - off] : 0;
        __syncthreads();
        ss[tid] += v;
        __syncthreads();
    }
    int run = (tid == 0) ? 0 : ss[tid - 1];
    for (int i = 0; i < ch; i++) {
        int idx = base + i;
        if (idx < N) { g_offs[idx] = run; run += g_hist[idx]; }
    }
    if (tid == 1023) g_offs[N] = ss[1023];
}

__global__ void k_scatter(const int* __restrict__ ei, int E) {
    int e = blockIdx.x * blockDim.x + threadIdx.x;
    if (e < E) {
        int r = ei[e];
        int idx = g_offs[r] + atomicAdd(&g_cur[r], 1);
        g_col[idx] = ei[E + e];
        g_row[idx] = r;
    }
}

// ---------------- per-layer node projections + zero magg/dx --------------
__global__ __launch_bounds__(256) void k_proj(const float* __restrict__ eW1,
                                              const float* __restrict__ eb1, int N) {
    __shared__ u64 sA[64 * 32];
    __shared__ u64 sB[64 * 32];
    __shared__ u64 sb1[32];
    __shared__ __align__(16) float hb[8][64];
    int tid = threadIdx.x;
    const float* W1a = eW1;
    const float* W1b = eW1 + 64 * 64;
    for (int idx = tid; idx < 2048; idx += 256) {
        int i = idx >> 5, j2 = idx & 31;
        sA[idx] = packxy(W1a[i * 64 + 2 * j2], W1a[i * 64 + 2 * j2 + 1]);
        sB[idx] = packxy(W1b[i * 64 + 2 * j2], W1b[i * 64 + 2 * j2 + 1]);
    }
    if (tid < 32) sb1[tid] = packxy(eb1[2 * tid], eb1[2 * tid + 1]);
    __syncthreads();
    int wid = tid >> 5, lane = tid & 31;
    for (int n = blockIdx.x * 8 + wid; n < N; n += gridDim.x * 8) {
        __syncwarp();
        hb[wid][lane]      = g_h[n * 64 + lane];
        hb[wid][lane + 32] = g_h[n * 64 + lane + 32];
        __syncwarp();
        u64 a1a = sb1[lane], a1b = 0ull;
        u64 a2a = 0ull, a2b = 0ull;
        #pragma unroll 8
        for (int i = 0; i < 64; i += 2) {
            u64 v0 = pack2(hb[wid][i]);
            u64 v1 = pack2(hb[wid][i + 1]);
            a1a = fma2(v0, sA[i * 32 + lane], a1a);
            a2a = fma2(v0, sB[i * 32 + lane], a2a);
            a1b = fma2(v1, sA[(i + 1) * 32 + lane], a1b);
            a2b = fma2(v1, sB[(i + 1) * 32 + lane], a2b);
        }
        ((float2*)(g_P1 + n * 64))[lane] = unpack(add2(a1a, a1b));
        ((float2*)(g_P2 + n * 64))[lane] = unpack(add2(a2a, a2b));
        // zero-init accumulators for this layer's edge pass
        ((float2*)(g_magg + n * 64))[lane] = make_float2(0.f, 0.f);
        if (lane < 3) g_dx[n * 3 + lane] = 0.f;
    }
}

// ---------------- edge kernel: FLAT edge-parallel over sorted CSR --------
// Warp handles 32 consecutive edges (all lanes valid). Per-node aggregation
// via segmented reduction: m staged through a padded smem transpose, lane =
// channel walks the 32 edges, flushing at row boundaries with atomicAdd.
__global__ __launch_bounds__(128, 4) void k_edge(const float* __restrict__ eW1,
                                                 const float* __restrict__ eW2,
                                                 const float* __restrict__ eb2,
                                                 const float* __restrict__ cW,
                                                 const float* __restrict__ cb, int E) {
    __shared__ __align__(16) u64 sW2[64 * 32];
    __shared__ u64 sb2[32];
    __shared__ __align__(16) float swd[64];
    __shared__ float scw[64];
    __shared__ float scb;
    __shared__ float ms[4][32 * 33];   // [warp][ch*33 + edge]
    __shared__ int   rows_s[4][32];
    int tid = threadIdx.x;
    for (int idx = tid; idx < 2048; idx += 128) {
        int i = idx >> 5, j2 = idx & 31;
        sW2[idx] = packxy(eW2[i * 64 + 2 * j2], eW2[i * 64 + 2 * j2 + 1]);
    }
    if (tid < 64) { swd[tid] = eW1[128 * 64 + tid]; scw[tid] = cW[tid]; }
    if (tid < 32) sb2[tid] = packxy(eb2[2 * tid], eb2[2 * tid + 1]);
    if (tid == 0) scb = cb[0];
    __syncthreads();
    int wid = tid >> 5, lane = tid & 31;
    float cbv = scb;
    int warp_g = blockIdx.x * 4 + wid;
    int nwarp = gridDim.x * 4;
    for (int base = warp_g * 32; base < E; base += nwarp * 32) {
        int e = base + lane;
        bool valid = (e < E);
        int ee = valid ? e : (E - 1);
        int r = g_row[ee];
        int c = g_col[ee];
        float r0 = g_x[r * 3]     - g_x[c * 3];
        float r1 = g_x[r * 3 + 1] - g_x[c * 3 + 1];
        float r2 = g_x[r * 3 + 2] - g_x[c * 3 + 2];
        float d2 = r0 * r0 + r1 * r1 + r2 * r2;
        const float4* p1 = (const float4*)(g_P1 + r * 64);
        const float4* p2 = (const float4*)(g_P2 + c * 64);
        u64 acc[32];
        #pragma unroll
        for (int j = 0; j < 32; j++) acc[j] = sb2[j];
        #pragma unroll 2
        for (int q = 0; q < 16; q++) {
            float4 tb = p1[q];
            float4 cv = p2[q];
            float4 wd = ((const float4*)swd)[q];
            float u0 = silu(tb.x + cv.x + d2 * wd.x);
            float u1 = silu(tb.y + cv.y + d2 * wd.y);
            float u2 = silu(tb.z + cv.z + d2 * wd.z);
            float u3 = silu(tb.w + cv.w + d2 * wd.w);
            u64 a0 = pack2(u0), a1 = pack2(u1), a2 = pack2(u2), a3 = pack2(u3);
            const ulonglong2* w0 = (const ulonglong2*)&sW2[(4 * q + 0) * 32];
            const ulonglong2* w1 = (const ulonglong2*)&sW2[(4 * q + 1) * 32];
            const ulonglong2* w2 = (const ulonglong2*)&sW2[(4 * q + 2) * 32];
            const ulonglong2* w3 = (const ulonglong2*)&sW2[(4 * q + 3) * 32];
            #pragma unroll
            for (int j = 0; j < 16; j++) {
                ulonglong2 b0 = w0[j];
                ulonglong2 b1 = w1[j];
                ulonglong2 b2 = w2[j];
                ulonglong2 b3 = w3[j];
                acc[2 * j]     = fma2(a0, b0.x, acc[2 * j]);
                acc[2 * j + 1] = fma2(a0, b0.y, acc[2 * j + 1]);
                acc[2 * j]     = fma2(a1, b1.x, acc[2 * j]);
                acc[2 * j + 1] = fma2(a1, b1.y, acc[2 * j + 1]);
                acc[2 * j]     = fma2(a2, b2.x, acc[2 * j]);
                acc[2 * j + 1] = fma2(a2, b2.y, acc[2 * j + 1]);
                acc[2 * j]     = fma2(a3, b3.x, acc[2 * j]);
                acc[2 * j + 1] = fma2(a3, b3.y, acc[2 * j + 1]);
            }
        }
        // silu -> m, coefficient dot
        float cd = cbv;
        #pragma unroll
        for (int j = 0; j < 32; j++) {
            float2 v = unpack(acc[j]);
            float m0 = silu(v.x), m1 = silu(v.y);
            acc[j] = packxy(m0, m1);
            cd += m0 * scw[2 * j] + m1 * scw[2 * j + 1];
        }
        float coef = valid ? tanhf(cd) : 0.f;
        if (!valid) {
            #pragma unroll
            for (int j = 0; j < 32; j++) acc[j] = 0ull;
        }
        // dx: per-lane float atomics (mostly single-address within warp)
        atomicAdd(&g_dx[r * 3 + 0], r0 * coef);
        atomicAdd(&g_dx[r * 3 + 1], r1 * coef);
        atomicAdd(&g_dx[r * 3 + 2], r2 * coef);
        // segment-end mask (rows nondecreasing within the window)
        int rnext = __shfl_down_sync(0xffffffffu, r, 1);
        bool segend = (lane == 31) || (rnext != r);
        unsigned endm = __ballot_sync(0xffffffffu, segend);
        rows_s[wid][lane] = r;
        __syncwarp();
        // two halves of 32 channels each
        #pragma unroll
        for (int h = 0; h < 2; h++) {
            #pragma unroll
            for (int j = 0; j < 16; j++) {
                float2 v = unpack(acc[h * 16 + j]);
                ms[wid][(2 * j) * 33 + lane]     = v.x;
                ms[wid][(2 * j + 1) * 33 + lane] = v.y;
            }
            __syncwarp();
            float sum = 0.f;
            const float* mrow = &ms[wid][lane * 33];
            #pragma unroll
            for (int e2 = 0; e2 < 32; e2++) {
                sum += mrow[e2];
                if ((endm >> e2) & 1u) {
                    int rr = rows_s[wid][e2];
                    atomicAdd(&g_magg[rr * 64 + h * 32 + lane], sum);
                    sum = 0.f;
                }
            }
            __syncwarp();
        }
    }
}

// ---------------- node update: h += MLP([h, magg]); x += dx -------------
__global__ __launch_bounds__(256) void k_node(const float* __restrict__ nW1,
                                              const float* __restrict__ nb1,
                                              const float* __restrict__ nW2,
                                              const float* __restrict__ nb2, int N) {
    __shared__ u64 sN1[128 * 32];
    __shared__ u64 sN2[64 * 32];
    __shared__ u64 snb1[32], snb2[32];
    __shared__ float inb[8][128];
    __shared__ float ub[8][64];
    int tid = threadIdx.x;
    for (int idx = tid; idx < 4096; idx += 256) {
        int i = idx >> 5, j2 = idx & 31;
        sN1[idx] = packxy(nW1[i * 64 + 2 * j2], nW1[i * 64 + 2 * j2 + 1]);
    }
    for (int idx = tid; idx < 2048; idx += 256) {
        int i = idx >> 5, j2 = idx & 31;
        sN2[idx] = packxy(nW2[i * 64 + 2 * j2], nW2[i * 64 + 2 * j2 + 1]);
    }
    if (tid < 32) {
        snb1[tid] = packxy(nb1[2 * tid], nb1[2 * tid + 1]);
        snb2[tid] = packxy(nb2[2 * tid], nb2[2 * tid + 1]);
    }
    __syncthreads();
    int wid = tid >> 5, lane = tid & 31;
    for (int n = blockIdx.x * 8 + wid; n < N; n += gridDim.x * 8) {
        __syncwarp();
        inb[wid][lane]      = g_h[n * 64 + lane];
        inb[wid][lane + 32] = g_h[n * 64 + lane + 32];
        inb[wid][lane + 64] = g_magg[n * 64 + lane];
        inb[wid][lane + 96] = g_magg[n * 64 + lane + 32];
        __syncwarp();
        u64 a0 = snb1[lane], a1 = 0ull, a2 = 0ull, a3 = 0ull;
        #pragma unroll 8
        for (int i = 0; i < 128; i += 4) {
            a0 = fma2(pack2(inb[wid][i]),     sN1[(i)*32 + lane],     a0);
            a1 = fma2(pack2(inb[wid][i + 1]), sN1[(i + 1) * 32 + lane], a1);
            a2 = fma2(pack2(inb[wid][i + 2]), sN1[(i + 2) * 32 + lane], a2);
            a3 = fma2(pack2(inb[wid][i + 3]), sN1[(i + 3) * 32 + lane], a3);
        }
        float2 t = unpack(add2(add2(a0, a1), add2(a2, a3)));
        ub[wid][2 * lane]     = silu(t.x);
        ub[wid][2 * lane + 1] = silu(t.y);
        __syncwarp();
        a0 = snb2[lane]; a1 = 0ull; a2 = 0ull; a3 = 0ull;
        #pragma unroll 8
        for (int i = 0; i < 64; i += 4) {
            a0 = fma2(pack2(ub[wid][i]),     sN2[(i)*32 + lane],     a0);
            a1 = fma2(pack2(ub[wid][i + 1]), sN2[(i + 1) * 32 + lane], a1);
            a2 = fma2(pack2(ub[wid][i + 2]), sN2[(i + 2) * 32 + lane], a2);
            a3 = fma2(pack2(ub[wid][i + 3]), sN2[(i + 3) * 32 + lane], a3);
        }
        float2 dh = unpack(add2(add2(a0, a1), add2(a2, a3)));
        float2* hp = (float2*)(g_h + n * 64);
        float2 hv = hp[lane];
        hv.x += dh.x;
        hv.y += dh.y;
        hp[lane] = hv;
        if (lane < 3) g_x[n * 3 + lane] += g_dx[n * 3 + lane];
    }
}

// ---------------- final: q per node + batch reductions -------------------
__global__ __launch_bounds__(256) void k_q(const float* __restrict__ qW1,
                                           const float* __restrict__ qb1,
                                           const float* __restrict__ qW2,
                                           const float* __restrict__ qb2,
                                           const int* __restrict__ batch, int N) {
    __shared__ u64 sQ[64 * 32];
    __shared__ u64 sqb[32];
    __shared__ float sw2[64];
    __shared__ float hb[8][64];
    __shared__ float sqb2;
    int tid = threadIdx.x;
    for (int idx = tid; idx < 2048; idx += 256) {
        int i = idx >> 5, j2 = idx & 31;
        sQ[idx] = packxy(qW1[i * 64 + 2 * j2], qW1[i * 64 + 2 * j2 + 1]);
    }
    if (tid < 32) sqb[tid] = packxy(qb1[2 * tid], qb1[2 * tid + 1]);
    if (tid < 64) sw2[tid] = qW2[tid];
    if (tid == 0) sqb2 = qb2[0];
    __syncthreads();
    int wid = tid >> 5, lane = tid & 31;
    for (int n = blockIdx.x * 8 + wid; n < N; n += gridDim.x * 8) {
        __syncwarp();
        hb[wid][lane]      = g_h[n * 64 + lane];
        hb[wid][lane + 32] = g_h[n * 64 + lane + 32];
        __syncwarp();
        u64 a0 = sqb[lane], a1 = 0ull;
        #pragma unroll 8
        for (int i = 0; i < 64; i += 2) {
            a0 = fma2(pack2(hb[wid][i]),     sQ[(i)*32 + lane],     a0);
            a1 = fma2(pack2(hb[wid][i + 1]), sQ[(i + 1) * 32 + lane], a1);
        }
        float2 t = unpack(add2(a0, a1));
        float cd = silu(t.x) * sw2[2 * lane] + silu(t.y) * sw2[2 * lane + 1];
        #pragma unroll
        for (int off = 16; off; off >>= 1) cd += __shfl_xor_sync(0xffffffffu, cd, off);
        if (lane == 0) {
            float q = cd + sqb2;
            int b = batch[n];
            float x0 = g_x[n * 3], x1 = g_x[n * 3 + 1], x2 = g_x[n * 3 + 2];
            atomicAdd(&g_qsum[b], q);
            atomicAdd(&g_qx[b * 3 + 0], q * x0);
            atomicAdd(&g_qx[b * 3 + 1], q * x1);
            atomicAdd(&g_qx[b * 3 + 2], q * x2);
            atomicAdd(&g_xsum[b * 3 + 0], x0);
            atomicAdd(&g_xsum[b * 3 + 1], x1);
            atomicAdd(&g_xsum[b * 3 + 2], x2);
            atomicAdd(&g_cnt[b], 1.0f);
        }
    }
}

__global__ void k_mu(float* __restrict__ out, int B) {
    int b = blockIdx.x * blockDim.x + threadIdx.x;
    if (b < B) {
        float c = fmaxf(g_cnt[b], 1.0f);
        float qs = g_qsum[b];
        #pragma unroll
        for (int k = 0; k < 3; k++) {
            float ctr = g_xsum[b * 3 + k] / c;
            out[b * 3 + k] = g_qx[b * 3 + k] - ctr * qs;
        }
    }
}

// ---------------- launch -------------------------------------------------
extern "C" void kernel_launch(void* const* d_in, const int* in_sizes, int n_in,
                              void* d_out, int out_size) {
    const int*   z    = (const int*)d_in[0];
    const float* pos  = (const float*)d_in[1];
    const int*   ei   = (const int*)d_in[2];
    const int*   bat  = (const int*)d_in[3];
    const float* emb  = (const float*)d_in[4];
    const float* eW1  = (const float*)d_in[5];
    const float* eb1  = (const float*)d_in[6];
    const float* eW2  = (const float*)d_in[7];
    const float* eb2  = (const float*)d_in[8];
    const float* cW   = (const float*)d_in[9];
    const float* cb   = (const float*)d_in[10];
    const float* nW1  = (const float*)d_in[11];
    const float* nb1  = (const float*)d_in[12];
    const float* nW2  = (const float*)d_in[13];
    const float* nb2  = (const float*)d_in[14];
    const float* qW1  = (const float*)d_in[15];
    const float* qb1  = (const float*)d_in[16];
    const float* qW2  = (const float*)d_in[17];
    const float* qb2  = (const float*)d_in[18];
    float* out = (float*)d_out;

    int N = in_sizes[0];
    int E = in_sizes[2] / 2;
    int B = out_size / 3;

    k_init<<<(N * 64 + 255) / 256, 256>>>(z, pos, emb, N, B);
    k_hist<<<(E + 255) / 256, 256>>>(ei, E);
    k_scan<<<1, 1024>>>(N);
    k_scatter<<<(E + 255) / 256, 256>>>(ei, E);

    const int nblk = 1184;
    const int eblk = 1184;  // 128-thread blocks, 4 edge-warps each, grid-stride
    for (int l = 0; l < 4; l++) {
        k_proj<<<nblk, 256>>>(eW1 + l * 129 * 64, eb1 + l * 64, N);
        k_edge<<<eblk, 128>>>(eW1 + l * 129 * 64, eW2 + l * 4096, eb2 + l * 64,
                              cW + l * 64, cb + l, E);
        k_node<<<nblk, 256>>>(nW1 + l * 128 * 64, nb1 + l * 64, nW2 + l * 4096,
                              nb2 + l * 64, N);
    }
    k_q<<<nblk, 256>>>(qW1, qb1, qW2, qb2, bat, N);
    k_mu<<<(B + 255) / 256, 256>>>(out, B);
}

// round 5
// speedup vs baseline: 2.3573x; 1.0696x over previous
#include <cuda_runtime.h>

#define NN 50000
#define EE 1600000
#define BBB 512

// ---------------- device scratch (static; no allocation) ----------------
__device__ float g_h[NN * 64];
__device__ float g_x[NN * 3];
__device__ float g_P1[NN * 64];
__device__ float g_P2[NN * 64];
__device__ float g_magg[NN * 64];
__device__ float g_dx[NN * 3];
__device__ int   g_hist[NN];
__device__ int   g_offs[NN + 1];
__device__ int   g_cur[NN];
__device__ int   g_col[EE];
__device__ int   g_row[EE];
__device__ float g_qsum[BBB];
__device__ float g_qx[BBB * 3];
__device__ float g_xsum[BBB * 3];
__device__ float g_cnt[BBB];

typedef unsigned long long u64;

// ---------------- packed f32x2 helpers ----------------------------------
__device__ __forceinline__ u64 fma2(u64 a, u64 b, u64 c) {
    u64 d;
    asm("fma.rn.f32x2 %0, %1, %2, %3;" : "=l"(d) : "l"(a), "l"(b), "l"(c));
    return d;
}
__device__ __forceinline__ u64 add2(u64 a, u64 b) {
    u64 d;
    asm("add.rn.f32x2 %0, %1, %2;" : "=l"(d) : "l"(a), "l"(b));
    return d;
}
__device__ __forceinline__ u64 pack2(float v) {
    u64 d;
    asm("mov.b64 %0, {%1, %1};" : "=l"(d) : "f"(v));
    return d;
}
__device__ __forceinline__ u64 packxy(float x, float y) {
    u64 d;
    asm("mov.b64 %0, {%1, %2};" : "=l"(d) : "f"(x), "f"(y));
    return d;
}
__device__ __forceinline__ float2 unpack(u64 v) {
    float2 f;
    asm("mov.b64 {%0, %1}, %2;" : "=f"(f.x), "=f"(f.y) : "l"(v));
    return f;
}

__device__ __forceinline__ float silu(float v) {
    float e = __expf(-v);
    return __fdividef(v, 1.0f + e);
}

// ---------------- init ---------------------------------------------------
__global__ void k_init(const int* __restrict__ z, const float* __restrict__ pos,
                       const float* __restrict__ emb, int N, int B) {
    int tid = blockIdx.x * blockDim.x + threadIdx.x;
    if (tid < N * 64) {
        int n = tid >> 6, k = tid & 63;
        g_h[tid] = emb[z[n] * 64 + k];
    }
    if (tid < N * 3) g_x[tid] = pos[tid];
    if (tid < N) { g_hist[tid] = 0; g_cur[tid] = 0; }
    if (tid < B) { g_qsum[tid] = 0.f; g_cnt[tid] = 0.f; }
    if (tid < B * 3) { g_qx[tid] = 0.f; g_xsum[tid] = 0.f; }
}

// ---------------- CSR build ----------------------------------------------
__global__ void k_hist(const int* __restrict__ ei, int E) {
    int e = blockIdx.x * blockDim.x + threadIdx.x;
    if (e < E) atomicAdd(&g_hist[ei[e]], 1);
}

__global__ void k_scan(int N) {
    __shared__ int ss[1024];
    int tid = threadIdx.x;
    int ch = (N + 1023) / 1024;
    int base = tid * ch;
    int s = 0;
    for (int i = 0; i < ch; i++) {
        int idx = base + i;
        if (idx < N) s += g_hist[idx];
    }
    ss[tid] = s;
    __syncthreads();
    for (int off = 1; off < 1024; off <<= 1) {
        int v = (tid >= off) ? ss[tid - off] : 0;
        __syncthreads();
        ss[tid] += v;
        __syncthreads();
    }
    int run = (tid == 0) ? 0 : ss[tid - 1];
    for (int i = 0; i < ch; i++) {
        int idx = base + i;
        if (idx < N) { g_offs[idx] = run; run += g_hist[idx]; }
    }
    if (tid == 1023) g_offs[N] = ss[1023];
}

__global__ void k_scatter(const int* __restrict__ ei, int E) {
    int e = blockIdx.x * blockDim.x + threadIdx.x;
    if (e < E) {
        int r = ei[e];
        int idx = g_offs[r] + atomicAdd(&g_cur[r], 1);
        g_col[idx] = ei[E + e];
        g_row[idx] = r;
    }
}

// ---------------- per-layer node projections + zero magg/dx --------------
__global__ __launch_bounds__(256) void k_proj(const float* __restrict__ eW1,
                                              const float* __restrict__ eb1, int N) {
    __shared__ u64 sA[64 * 32];
    __shared__ u64 sB[64 * 32];
    __shared__ u64 sb1[32];
    __shared__ __align__(16) float hb[8][64];
    int tid = threadIdx.x;
    const float* W1a = eW1;
    const float* W1b = eW1 + 64 * 64;
    for (int idx = tid; idx < 2048; idx += 256) {
        int i = idx >> 5, j2 = idx & 31;
        sA[idx] = packxy(W1a[i * 64 + 2 * j2], W1a[i * 64 + 2 * j2 + 1]);
        sB[idx] = packxy(W1b[i * 64 + 2 * j2], W1b[i * 64 + 2 * j2 + 1]);
    }
    if (tid < 32) sb1[tid] = packxy(eb1[2 * tid], eb1[2 * tid + 1]);
    __syncthreads();
    int wid = tid >> 5, lane = tid & 31;
    for (int n = blockIdx.x * 8 + wid; n < N; n += gridDim.x * 8) {
        __syncwarp();
        hb[wid][lane]      = g_h[n * 64 + lane];
        hb[wid][lane + 32] = g_h[n * 64 + lane + 32];
        __syncwarp();
        u64 a1a = sb1[lane], a1b = 0ull;
        u64 a2a = 0ull, a2b = 0ull;
        #pragma unroll 8
        for (int i = 0; i < 64; i += 2) {
            u64 v0 = pack2(hb[wid][i]);
            u64 v1 = pack2(hb[wid][i + 1]);
            a1a = fma2(v0, sA[i * 32 + lane], a1a);
            a2a = fma2(v0, sB[i * 32 + lane], a2a);
            a1b = fma2(v1, sA[(i + 1) * 32 + lane], a1b);
            a2b = fma2(v1, sB[(i + 1) * 32 + lane], a2b);
        }
        ((float2*)(g_P1 + n * 64))[lane] = unpack(add2(a1a, a1b));
        ((float2*)(g_P2 + n * 64))[lane] = unpack(add2(a2a, a2b));
        ((float2*)(g_magg + n * 64))[lane] = make_float2(0.f, 0.f);
        if (lane < 3) g_dx[n * 3 + lane] = 0.f;
    }
}

// ---------------- edge kernel: flat edge-parallel, staged P2 -------------
// Dynamic smem layout: [0,16384) sW2 (u64[2048]);
//                      [16384, 16384+4*8192) per-warp tile (float4[512]):
//                        first used as swizzled P2 stage, then reused as the
//                        [ch][edge] transpose buffer for segmented reduce.
// NOTE: needs cudaFuncAttributeMaxDynamicSharedMemorySize = 49152 (set in
// kernel_launch) because dynamic 48KB + ~1.3KB static exceeds the default.
__global__ __launch_bounds__(128, 4) void k_edge(const float* __restrict__ eW1,
                                                 const float* __restrict__ eW2,
                                                 const float* __restrict__ eb2,
                                                 const float* __restrict__ cW,
                                                 const float* __restrict__ cb, int E) {
    extern __shared__ __align__(16) char dyn[];
    u64* sW2 = (u64*)dyn;
    __shared__ u64 sb2[32];
    __shared__ __align__(16) float swd[64];
    __shared__ float scw[64];
    __shared__ float scb;
    __shared__ int   rows_s[4][32];
    int tid = threadIdx.x;
    for (int idx = tid; idx < 2048; idx += 128) {
        int i = idx >> 5, j2 = idx & 31;
        sW2[idx] = packxy(eW2[i * 64 + 2 * j2], eW2[i * 64 + 2 * j2 + 1]);
    }
    if (tid < 64) { swd[tid] = eW1[128 * 64 + tid]; scw[tid] = cW[tid]; }
    if (tid < 32) sb2[tid] = packxy(eb2[2 * tid], eb2[2 * tid + 1]);
    if (tid == 0) scb = cb[0];
    __syncthreads();
    int wid = tid >> 5, lane = tid & 31;
    float4* sp2 = (float4*)(dyn + 16384) + wid * 512;   // 32 nodes x 16 f4, swizzled
    float*  ms  = (float*)sp2;                           // reuse: [ch*33 + e]
    float cbv = scb;
    int half = lane >> 4;
    int fidx = lane & 15;
    int lane15 = lane & 15;
    int warp_g = blockIdx.x * 4 + wid;
    int nwarp = gridDim.x * 4;
    for (int base = warp_g * 32; base < E; base += nwarp * 32) {
        int e = base + lane;
        bool valid = (e < E);
        int ee = valid ? e : (E - 1);
        int r = g_row[ee];
        int c = g_col[ee];
        // ---- stage P2[c] for the 32 edge-cols, coalesced + swizzled ----
        __syncwarp();
        #pragma unroll
        for (int i = 0; i < 16; i++) {
            int node = 2 * i + half;
            int cc = __shfl_sync(0xffffffffu, c, node);
            float4 v = ((const float4*)(g_P2 + cc * 64))[fidx];
            sp2[node * 16 + (fidx ^ (node & 15))] = v;
        }
        __syncwarp();
        float r0 = g_x[r * 3]     - g_x[c * 3];
        float r1 = g_x[r * 3 + 1] - g_x[c * 3 + 1];
        float r2 = g_x[r * 3 + 2] - g_x[c * 3 + 2];
        float d2 = r0 * r0 + r1 * r1 + r2 * r2;
        const float4* p1 = (const float4*)(g_P1 + r * 64);   // rows sorted -> broadcast
        u64 acc[32];
        #pragma unroll
        for (int j = 0; j < 32; j++) acc[j] = sb2[j];
        #pragma unroll 2
        for (int q = 0; q < 16; q++) {
            float4 tb = p1[q];
            float4 cv = sp2[lane * 16 + (q ^ lane15)];
            float4 wd = ((const float4*)swd)[q];
            float u0 = silu(tb.x + cv.x + d2 * wd.x);
            float u1 = silu(tb.y + cv.y + d2 * wd.y);
            float u2 = silu(tb.z + cv.z + d2 * wd.z);
            float u3 = silu(tb.w + cv.w + d2 * wd.w);
            u64 a0 = pack2(u0), a1 = pack2(u1), a2 = pack2(u2), a3 = pack2(u3);
            const ulonglong2* w0 = (const ulonglong2*)&sW2[(4 * q + 0) * 32];
            const ulonglong2* w1 = (const ulonglong2*)&sW2[(4 * q + 1) * 32];
            const ulonglong2* w2 = (const ulonglong2*)&sW2[(4 * q + 2) * 32];
            const ulonglong2* w3 = (const ulonglong2*)&sW2[(4 * q + 3) * 32];
            #pragma unroll
            for (int j = 0; j < 16; j++) {
                ulonglong2 b0 = w0[j];
                ulonglong2 b1 = w1[j];
                ulonglong2 b2 = w2[j];
                ulonglong2 b3 = w3[j];
                acc[2 * j]     = fma2(a0, b0.x, acc[2 * j]);
                acc[2 * j + 1] = fma2(a0, b0.y, acc[2 * j + 1]);
                acc[2 * j]     = fma2(a1, b1.x, acc[2 * j]);
                acc[2 * j + 1] = fma2(a1, b1.y, acc[2 * j + 1]);
                acc[2 * j]     = fma2(a2, b2.x, acc[2 * j]);
                acc[2 * j + 1] = fma2(a2, b2.y, acc[2 * j + 1]);
                acc[2 * j]     = fma2(a3, b3.x, acc[2 * j]);
                acc[2 * j + 1] = fma2(a3, b3.y, acc[2 * j + 1]);
            }
        }
        // silu -> m, coefficient dot
        float cd = cbv;
        #pragma unroll
        for (int j = 0; j < 32; j++) {
            float2 v = unpack(acc[j]);
            float m0 = silu(v.x), m1 = silu(v.y);
            acc[j] = packxy(m0, m1);
            cd += m0 * scw[2 * j] + m1 * scw[2 * j + 1];
        }
        float coef = valid ? tanhf(cd) : 0.f;
        if (!valid) {
            #pragma unroll
            for (int j = 0; j < 32; j++) acc[j] = 0ull;
        }
        atomicAdd(&g_dx[r * 3 + 0], r0 * coef);
        atomicAdd(&g_dx[r * 3 + 1], r1 * coef);
        atomicAdd(&g_dx[r * 3 + 2], r2 * coef);
        // segmented reduce over sorted rows
        int rnext = __shfl_down_sync(0xffffffffu, r, 1);
        bool segend = (lane == 31) || (rnext != r);
        unsigned endm = __ballot_sync(0xffffffffu, segend);
        rows_s[wid][lane] = r;
        __syncwarp();   // sp2 reads done; reuse as ms
        #pragma unroll
        for (int h = 0; h < 2; h++) {
            #pragma unroll
            for (int j = 0; j < 16; j++) {
                float2 v = unpack(acc[h * 16 + j]);
                ms[(2 * j) * 33 + lane]     = v.x;
                ms[(2 * j + 1) * 33 + lane] = v.y;
            }
            __syncwarp();
            float sum = 0.f;
            const float* mrow = &ms[lane * 33];
            #pragma unroll
            for (int e2 = 0; e2 < 32; e2++) {
                sum += mrow[e2];
                if ((endm >> e2) & 1u) {
                    int rr = rows_s[wid][e2];
                    atomicAdd(&g_magg[rr * 64 + h * 32 + lane], sum);
                    sum = 0.f;
                }
            }
            __syncwarp();
        }
    }
}

// ---------------- node update: h += MLP([h, magg]); x += dx -------------
__global__ __launch_bounds__(256) void k_node(const float* __restrict__ nW1,
                                              const float* __restrict__ nb1,
                                              const float* __restrict__ nW2,
                                              const float* __restrict__ nb2, int N) {
    __shared__ u64 sN1[128 * 32];
    __shared__ u64 sN2[64 * 32];
    __shared__ u64 snb1[32], snb2[32];
    __shared__ float inb[8][128];
    __shared__ float ub[8][64];
    int tid = threadIdx.x;
    for (int idx = tid; idx < 4096; idx += 256) {
        int i = idx >> 5, j2 = idx & 31;
        sN1[idx] = packxy(nW1[i * 64 + 2 * j2], nW1[i * 64 + 2 * j2 + 1]);
    }
    for (int idx = tid; idx < 2048; idx += 256) {
        int i = idx >> 5, j2 = idx & 31;
        sN2[idx] = packxy(nW2[i * 64 + 2 * j2], nW2[i * 64 + 2 * j2 + 1]);
    }
    if (tid < 32) {
        snb1[tid] = packxy(nb1[2 * tid], nb1[2 * tid + 1]);
        snb2[tid] = packxy(nb2[2 * tid], nb2[2 * tid + 1]);
    }
    __syncthreads();
    int wid = tid >> 5, lane = tid & 31;
    for (int n = blockIdx.x * 8 + wid; n < N; n += gridDim.x * 8) {
        __syncwarp();
        inb[wid][lane]      = g_h[n * 64 + lane];
        inb[wid][lane + 32] = g_h[n * 64 + lane + 32];
        inb[wid][lane + 64] = g_magg[n * 64 + lane];
        inb[wid][lane + 96] = g_magg[n * 64 + lane + 32];
        __syncwarp();
        u64 a0 = snb1[lane], a1 = 0ull, a2 = 0ull, a3 = 0ull;
        #pragma unroll 8
        for (int i = 0; i < 128; i += 4) {
            a0 = fma2(pack2(inb[wid][i]),     sN1[(i)*32 + lane],     a0);
            a1 = fma2(pack2(inb[wid][i + 1]), sN1[(i + 1) * 32 + lane], a1);
            a2 = fma2(pack2(inb[wid][i + 2]), sN1[(i + 2) * 32 + lane], a2);
            a3 = fma2(pack2(inb[wid][i + 3]), sN1[(i + 3) * 32 + lane], a3);
        }
        float2 t = unpack(add2(add2(a0, a1), add2(a2, a3)));
        ub[wid][2 * lane]     = silu(t.x);
        ub[wid][2 * lane + 1] = silu(t.y);
        __syncwarp();
        a0 = snb2[lane]; a1 = 0ull; a2 = 0ull; a3 = 0ull;
        #pragma unroll 8
        for (int i = 0; i < 64; i += 4) {
            a0 = fma2(pack2(ub[wid][i]),     sN2[(i)*32 + lane],     a0);
            a1 = fma2(pack2(ub[wid][i + 1]), sN2[(i + 1) * 32 + lane], a1);
            a2 = fma2(pack2(ub[wid][i + 2]), sN2[(i + 2) * 32 + lane], a2);
            a3 = fma2(pack2(ub[wid][i + 3]), sN2[(i + 3) * 32 + lane], a3);
        }
        float2 dh = unpack(add2(add2(a0, a1), add2(a2, a3)));
        float2* hp = (float2*)(g_h + n * 64);
        float2 hv = hp[lane];
        hv.x += dh.x;
        hv.y += dh.y;
        hp[lane] = hv;
        if (lane < 3) g_x[n * 3 + lane] += g_dx[n * 3 + lane];
    }
}

// ---------------- final: q per node + batch reductions -------------------
__global__ __launch_bounds__(256) void k_q(const float* __restrict__ qW1,
                                           const float* __restrict__ qb1,
                                           const float* __restrict__ qW2,
                                           const float* __restrict__ qb2,
                                           const int* __restrict__ batch, int N) {
    __shared__ u64 sQ[64 * 32];
    __shared__ u64 sqb[32];
    __shared__ float sw2[64];
    __shared__ float hb[8][64];
    __shared__ float sqb2;
    int tid = threadIdx.x;
    for (int idx = tid; idx < 2048; idx += 256) {
        int i = idx >> 5, j2 = idx & 31;
        sQ[idx] = packxy(qW1[i * 64 + 2 * j2], qW1[i * 64 + 2 * j2 + 1]);
    }
    if (tid < 32) sqb[tid] = packxy(qb1[2 * tid], qb1[2 * tid + 1]);
    if (tid < 64) sw2[tid] = qW2[tid];
    if (tid == 0) sqb2 = qb2[0];
    __syncthreads();
    int wid = tid >> 5, lane = tid & 31;
    for (int n = blockIdx.x * 8 + wid; n < N; n += gridDim.x * 8) {
        __syncwarp();
        hb[wid][lane]      = g_h[n * 64 + lane];
        hb[wid][lane + 32] = g_h[n * 64 + lane + 32];
        __syncwarp();
        u64 a0 = sqb[lane], a1 = 0ull;
        #pragma unroll 8
        for (int i = 0; i < 64; i += 2) {
            a0 = fma2(pack2(hb[wid][i]),     sQ[(i)*32 + lane],     a0);
            a1 = fma2(pack2(hb[wid][i + 1]), sQ[(i + 1) * 32 + lane], a1);
        }
        float2 t = unpack(add2(a0, a1));
        float cd = silu(t.x) * sw2[2 * lane] + silu(t.y) * sw2[2 * lane + 1];
        #pragma unroll
        for (int off = 16; off; off >>= 1) cd += __shfl_xor_sync(0xffffffffu, cd, off);
        if (lane == 0) {
            float q = cd + sqb2;
            int b = batch[n];
            float x0 = g_x[n * 3], x1 = g_x[n * 3 + 1], x2 = g_x[n * 3 + 2];
            atomicAdd(&g_qsum[b], q);
            atomicAdd(&g_qx[b * 3 + 0], q * x0);
            atomicAdd(&g_qx[b * 3 + 1], q * x1);
            atomicAdd(&g_qx[b * 3 + 2], q * x2);
            atomicAdd(&g_xsum[b * 3 + 0], x0);
            atomicAdd(&g_xsum[b * 3 + 1], x1);
            atomicAdd(&g_xsum[b * 3 + 2], x2);
            atomicAdd(&g_cnt[b], 1.0f);
        }
    }
}

__global__ void k_mu(float* __restrict__ out, int B) {
    int b = blockIdx.x * blockDim.x + threadIdx.x;
    if (b < B) {
        float c = fmaxf(g_cnt[b], 1.0f);
        float qs = g_qsum[b];
        #pragma unroll
        for (int k = 0; k < 3; k++) {
            float ctr = g_xsum[b * 3 + k] / c;
            out[b * 3 + k] = g_qx[b * 3 + k] - ctr * qs;
        }
    }
}

// ---------------- launch -------------------------------------------------
extern "C" void kernel_launch(void* const* d_in, const int* in_sizes, int n_in,
                              void* d_out, int out_size) {
    const int*   z    = (const int*)d_in[0];
    const float* pos  = (const float*)d_in[1];
    const int*   ei   = (const int*)d_in[2];
    const int*   bat  = (const int*)d_in[3];
    const float* emb  = (const float*)d_in[4];
    const float* eW1  = (const float*)d_in[5];
    const float* eb1  = (const float*)d_in[6];
    const float* eW2  = (const float*)d_in[7];
    const float* eb2  = (const float*)d_in[8];
    const float* cW   = (const float*)d_in[9];
    const float* cb   = (const float*)d_in[10];
    const float* nW1  = (const float*)d_in[11];
    const float* nb1  = (const float*)d_in[12];
    const float* nW2  = (const float*)d_in[13];
    const float* nb2  = (const float*)d_in[14];
    const float* qW1  = (const float*)d_in[15];
    const float* qb1  = (const float*)d_in[16];
    const float* qW2  = (const float*)d_in[17];
    const float* qb2  = (const float*)d_in[18];
    float* out = (float*)d_out;

    int N = in_sizes[0];
    int E = in_sizes[2] / 2;
    int B = out_size / 3;

    const int esmem = 16384 + 4 * 8192;   // sW2 + per-warp stage/reduce tiles = 48KB
    // Opt in to >default dynamic smem (idempotent host-side attribute set;
    // not a stream op, legal during graph capture).
    cudaFuncSetAttribute(k_edge, cudaFuncAttributeMaxDynamicSharedMemorySize, esmem);

    k_init<<<(N * 64 + 255) / 256, 256>>>(z, pos, emb, N, B);
    k_hist<<<(E + 255) / 256, 256>>>(ei, E);
    k_scan<<<1, 1024>>>(N);
    k_scatter<<<(E + 255) / 256, 256>>>(ei, E);

    const int nblk = 1184;
    const int eblk = 1184;
    for (int l = 0; l < 4; l++) {
        k_proj<<<nblk, 256>>>(eW1 + l * 129 * 64, eb1 + l * 64, N);
        k_edge<<<eblk, 128, esmem>>>(eW1 + l * 129 * 64, eW2 + l * 4096, eb2 + l * 64,
                                     cW + l * 64, cb + l, E);
        k_node<<<nblk, 256>>>(nW1 + l * 128 * 64, nb1 + l * 64, nW2 + l * 4096,
                              nb2 + l * 64, N);
    }
    k_q<<<nblk, 256>>>(qW1, qb1, qW2, qb2, bat, N);
    k_mu<<<(B + 255) / 256, 256>>>(out, B);
}